// round 1
// baseline (speedup 1.0000x reference)
#include <cuda_runtime.h>
#include <cuda_bf16.h>
#include <cstdint>

// Problem constants (from reference)
#define N_MAX 100000
#define E_MAX 1600000
#define D 128
#define N_GIN 3

// ---------------- scratch (device globals; no allocation allowed) ----------
__device__ float g_bufA[N_MAX * D];
__device__ float g_bufB[N_MAX * D];
__device__ int   g_deg[N_MAX];
__device__ int   g_off[N_MAX];
__device__ int   g_cursor[N_MAX];
__device__ int   g_csr[E_MAX];
__device__ int   g_bsums[256];

// ---------------- f32x2 helpers (Blackwell packed fp32) --------------------
__device__ __forceinline__ unsigned long long pack2(float lo, float hi) {
    unsigned long long r;
    asm("mov.b64 %0, {%1, %2};" : "=l"(r) : "f"(lo), "f"(hi));
    return r;
}
__device__ __forceinline__ void unpack2(unsigned long long v, float& lo, float& hi) {
    asm("mov.b64 {%0, %1}, %2;" : "=f"(lo), "=f"(hi) : "l"(v));
}
__device__ __forceinline__ void fma2(unsigned long long& d,
                                     unsigned long long a,
                                     unsigned long long b) {
    asm("fma.rn.f32x2 %0, %1, %2, %0;" : "+l"(d) : "l"(a), "l"(b));
}

// ---------------- CSR build -------------------------------------------------
__global__ void k_zero_deg(int* deg, int n) {
    int i = blockIdx.x * blockDim.x + threadIdx.x;
    if (i < n) deg[i] = 0;
}

__global__ void k_count_deg(const int* __restrict__ dst, int* __restrict__ deg, int e) {
    int i = blockIdx.x * blockDim.x + threadIdx.x;
    if (i < e) atomicAdd(&deg[dst[i]], 1);
}

// block-wise exclusive scan (block = 1024)
__global__ void k_scan_block(const int* __restrict__ deg, int* __restrict__ off,
                             int* __restrict__ bsums, int n) {
    __shared__ int warp_sums[32];
    int tid = threadIdx.x;
    int gid = blockIdx.x * 1024 + tid;
    int v = (gid < n) ? deg[gid] : 0;
    int x = v;
#pragma unroll
    for (int s = 1; s < 32; s <<= 1) {
        int y = __shfl_up_sync(0xffffffffu, x, s);
        if ((tid & 31) >= s) x += y;
    }
    if ((tid & 31) == 31) warp_sums[tid >> 5] = x;
    __syncthreads();
    if (tid < 32) {
        int w = warp_sums[tid];
        int xw = w;
#pragma unroll
        for (int s = 1; s < 32; s <<= 1) {
            int y = __shfl_up_sync(0xffffffffu, xw, s);
            if (tid >= s) xw += y;
        }
        warp_sums[tid] = xw - w;  // exclusive warp offset
        if (tid == 31) bsums[blockIdx.x] = xw;  // block total
    }
    __syncthreads();
    int excl = x - v + warp_sums[tid >> 5];
    if (gid < n) off[gid] = excl;
}

__global__ void k_scan_bsums(int* bsums, int nb) {
    if (threadIdx.x == 0 && blockIdx.x == 0) {
        int acc = 0;
        for (int i = 0; i < nb; ++i) { int t = bsums[i]; bsums[i] = acc; acc += t; }
    }
}

__global__ void k_add_offsets(int* __restrict__ off, int* __restrict__ cursor,
                              const int* __restrict__ bsums, int n) {
    int i = blockIdx.x * blockDim.x + threadIdx.x;
    if (i < n) {
        int o = off[i] + bsums[i >> 10];
        off[i] = o;
        cursor[i] = o;
    }
}

__global__ void k_csr_fill(const int* __restrict__ src, const int* __restrict__ dst,
                           int* __restrict__ cursor, int* __restrict__ csr, int e) {
    int i = blockIdx.x * blockDim.x + threadIdx.x;
    if (i < e) {
        int pos = atomicAdd(&cursor[dst[i]], 1);
        csr[pos] = src[i];
    }
}

// ---------------- aggregation: z = (1+eps)*h + mean_{nbr} h[nbr] -----------
// warp per node, float4 per lane (lane covers dims lane*4 .. lane*4+3)
__global__ void k_aggregate_z(const float* __restrict__ h,
                              const int* __restrict__ off,
                              const int* __restrict__ deg,
                              const int* __restrict__ csr,
                              const float* __restrict__ eps, int l,
                              float* __restrict__ z, int n) {
    int warp = (blockIdx.x * blockDim.x + threadIdx.x) >> 5;
    int lane = threadIdx.x & 31;
    if (warp >= n) return;
    int start = off[warp];
    int d = deg[warp];
    float inv = 1.0f / (float)((d > 0) ? d : 1);
    const float4* h4 = (const float4*)h;

    float4 acc = make_float4(0.f, 0.f, 0.f, 0.f);
    int j = 0;
    for (; j + 4 <= d; j += 4) {
        int nb0 = csr[start + j + 0];
        int nb1 = csr[start + j + 1];
        int nb2 = csr[start + j + 2];
        int nb3 = csr[start + j + 3];
        float4 v0 = __ldg(&h4[nb0 * 32 + lane]);
        float4 v1 = __ldg(&h4[nb1 * 32 + lane]);
        float4 v2 = __ldg(&h4[nb2 * 32 + lane]);
        float4 v3 = __ldg(&h4[nb3 * 32 + lane]);
        acc.x += v0.x + v1.x + v2.x + v3.x;
        acc.y += v0.y + v1.y + v2.y + v3.y;
        acc.z += v0.z + v1.z + v2.z + v3.z;
        acc.w += v0.w + v1.w + v2.w + v3.w;
    }
    for (; j < d; ++j) {
        int nb = csr[start + j];
        float4 v = __ldg(&h4[nb * 32 + lane]);
        acc.x += v.x; acc.y += v.y; acc.z += v.z; acc.w += v.w;
    }
    float e1 = 1.0f + eps[l];
    float4 hv = h4[warp * 32 + lane];
    float4 zz;
    zz.x = e1 * hv.x + inv * acc.x;
    zz.y = e1 * hv.y + inv * acc.y;
    zz.z = e1 * hv.z + inv * acc.z;
    zz.w = e1 * hv.w + inv * acc.w;
    ((float4*)z)[warp * 32 + lane] = zz;
}

// ---------------- GEMM: C = lrelu(A @ W + b), A [n,128], W [128,128] --------
// 128x128 block tile, 256 threads, 8 rows x 8 cols (4 f32x2 col-pairs) each.
#define ASTR 132
__global__ void k_gemm_bias_lrelu(const float* __restrict__ A,
                                  const float* __restrict__ W,
                                  const float* __restrict__ bias,
                                  float* __restrict__ C, int n) {
    extern __shared__ float sm[];
    float* As = sm;                 // [128][132]
    float* Ws = sm + 128 * ASTR;    // [128][128]

    int t = threadIdx.x;            // 0..255
    int row0 = blockIdx.x * 128;

    // load W tile (row-major [k][c]) — coalesced float4
    {
        const float4* Wg = (const float4*)W;
        float4* Ws4 = (float4*)Ws;
#pragma unroll
        for (int i = 0; i < 16; ++i) Ws4[t + i * 256] = Wg[t + i * 256];
    }
    // load A tile row-major padded — coalesced float4, conflict-free STS
    {
#pragma unroll
        for (int it = 0; it < 16; ++it) {
            int item = t + it * 256;   // 0..4095
            int r = item >> 5;         // row 0..127
            int kc = item & 31;        // float4 chunk along k
            int gr = row0 + r;
            float4 v = (gr < n) ? ((const float4*)A)[gr * 32 + kc]
                                : make_float4(0.f, 0.f, 0.f, 0.f);
            *(float4*)&As[r * ASTR + kc * 4] = v;
        }
    }
    __syncthreads();

    int lane = t & 31;
    int half = lane >> 4;            // 0/1
    int cidx = lane & 15;            // col group
    int rowg = ((t >> 5) << 1) + half;   // 0..15 ; thread rows = rowg + 16*i
    int c0 = cidx * 8;

    unsigned long long acc[8][4];
#pragma unroll
    for (int i = 0; i < 8; ++i)
#pragma unroll
        for (int jj = 0; jj < 4; ++jj) acc[i][jj] = 0ull;

    const float* aBase = &As[rowg * ASTR];

#pragma unroll 8
    for (int k = 0; k < 128; ++k) {
        float4 wA = *(const float4*)&Ws[k * 128 + c0];
        float4 wB = *(const float4*)&Ws[k * 128 + c0 + 4];
        unsigned long long w01 = pack2(wA.x, wA.y);
        unsigned long long w23 = pack2(wA.z, wA.w);
        unsigned long long w45 = pack2(wB.x, wB.y);
        unsigned long long w67 = pack2(wB.z, wB.w);
#pragma unroll
        for (int i = 0; i < 8; ++i) {
            float a = aBase[i * 16 * ASTR + k];
            unsigned long long a2 = pack2(a, a);
            fma2(acc[i][0], a2, w01);
            fma2(acc[i][1], a2, w23);
            fma2(acc[i][2], a2, w45);
            fma2(acc[i][3], a2, w67);
        }
    }

    // epilogue: bias + leaky relu (slope 0.01), float4 stores
    float bv[8];
#pragma unroll
    for (int c = 0; c < 8; ++c) bv[c] = bias[c0 + c];

#pragma unroll
    for (int i = 0; i < 8; ++i) {
        int gr = row0 + rowg + 16 * i;
        if (gr < n) {
            float out[8];
#pragma unroll
            for (int jj = 0; jj < 4; ++jj) {
                float lo, hi;
                unpack2(acc[i][jj], lo, hi);
                out[2 * jj] = lo;
                out[2 * jj + 1] = hi;
            }
#pragma unroll
            for (int c = 0; c < 8; ++c) {
                float v = out[c] + bv[c];
                out[c] = (v > 0.f) ? v : 0.01f * v;
            }
            float4* Cp = (float4*)&C[gr * 128 + c0];
            Cp[0] = make_float4(out[0], out[1], out[2], out[3]);
            Cp[1] = make_float4(out[4], out[5], out[6], out[7]);
        }
    }
}

// ---------------- output projection: n_out = emb @ Wout + bout --------------
__global__ void k_out_proj(const float* __restrict__ emb,
                           const float* __restrict__ Wout,
                           const float* __restrict__ bout,
                           float* __restrict__ nout, int n) {
    int warp = (blockIdx.x * blockDim.x + threadIdx.x) >> 5;
    int lane = threadIdx.x & 31;
    if (warp >= n) return;
    float4 h = ((const float4*)emb)[warp * 32 + lane];
    int d0 = lane * 4;
    float s0 = h.x * Wout[(d0 + 0) * 2 + 0] + h.y * Wout[(d0 + 1) * 2 + 0]
             + h.z * Wout[(d0 + 2) * 2 + 0] + h.w * Wout[(d0 + 3) * 2 + 0];
    float s1 = h.x * Wout[(d0 + 0) * 2 + 1] + h.y * Wout[(d0 + 1) * 2 + 1]
             + h.z * Wout[(d0 + 2) * 2 + 1] + h.w * Wout[(d0 + 3) * 2 + 1];
#pragma unroll
    for (int s = 16; s > 0; s >>= 1) {
        s0 += __shfl_xor_sync(0xffffffffu, s0, s);
        s1 += __shfl_xor_sync(0xffffffffu, s1, s);
    }
    if (lane == 0) {
        nout[warp * 2 + 0] = s0 + bout[0];
        nout[warp * 2 + 1] = s1 + bout[1];
    }
}

// ---------------- launch -----------------------------------------------------
extern "C" void kernel_launch(void* const* d_in, const int* in_sizes, int n_in,
                              void* d_out, int out_size) {
    const float* x    = (const float*)d_in[0];
    const int*   src  = (const int*)d_in[1];
    const int*   dst  = (const int*)d_in[2];
    const float* W1   = (const float*)d_in[3];
    const float* b1   = (const float*)d_in[4];
    const float* W2   = (const float*)d_in[5];
    const float* b2   = (const float*)d_in[6];
    const float* eps  = (const float*)d_in[7];
    const float* Wout = (const float*)d_in[8];
    const float* bout = (const float*)d_in[9];

    const int n = in_sizes[0] / D;     // 100000
    const int e = in_sizes[1];         // 1600000

    float* nout = (float*)d_out;                 // [n, 2]
    float* emb  = (float*)d_out + (size_t)n * 2; // [n, 128]

    // resolve device-global scratch addresses
    float *bufA, *bufB;
    int *deg, *off, *cursor, *csr, *bsums;
    cudaGetSymbolAddress((void**)&bufA,   g_bufA);
    cudaGetSymbolAddress((void**)&bufB,   g_bufB);
    cudaGetSymbolAddress((void**)&deg,    g_deg);
    cudaGetSymbolAddress((void**)&off,    g_off);
    cudaGetSymbolAddress((void**)&cursor, g_cursor);
    cudaGetSymbolAddress((void**)&csr,    g_csr);
    cudaGetSymbolAddress((void**)&bsums,  g_bsums);

    const int smem_gemm = (128 * ASTR + 128 * 128) * sizeof(float); // 133120
    cudaFuncSetAttribute(k_gemm_bias_lrelu,
                         cudaFuncAttributeMaxDynamicSharedMemorySize, smem_gemm);

    // ---- CSR build ----
    int nb = (n + 1023) / 1024;
    k_zero_deg<<<(n + 255) / 256, 256>>>(deg, n);
    k_count_deg<<<(e + 255) / 256, 256>>>(dst, deg, e);
    k_scan_block<<<nb, 1024>>>(deg, off, bsums, n);
    k_scan_bsums<<<1, 32>>>(bsums, nb);
    k_add_offsets<<<(n + 255) / 256, 256>>>(off, cursor, bsums, n);
    k_csr_fill<<<(e + 255) / 256, 256>>>(src, dst, cursor, csr, e);

    // ---- 3 GIN layers ----
    const int agg_blocks = (n * 32 + 255) / 256;
    const int gemm_blocks = (n + 127) / 128;

    // layer 0: x -> bufB -> bufA -> bufB
    k_aggregate_z<<<agg_blocks, 256>>>(x, off, deg, csr, eps, 0, bufB, n);
    k_gemm_bias_lrelu<<<gemm_blocks, 256, smem_gemm>>>(bufB, W1 + 0 * D * D, b1 + 0 * D, bufA, n);
    k_gemm_bias_lrelu<<<gemm_blocks, 256, smem_gemm>>>(bufA, W2 + 0 * D * D, b2 + 0 * D, bufB, n);

    // layer 1: bufB -> bufA -> bufB -> bufA
    k_aggregate_z<<<agg_blocks, 256>>>(bufB, off, deg, csr, eps, 1, bufA, n);
    k_gemm_bias_lrelu<<<gemm_blocks, 256, smem_gemm>>>(bufA, W1 + 1 * D * D, b1 + 1 * D, bufB, n);
    k_gemm_bias_lrelu<<<gemm_blocks, 256, smem_gemm>>>(bufB, W2 + 1 * D * D, b2 + 1 * D, bufA, n);

    // layer 2: bufA -> bufB -> bufA -> emb (direct to output)
    k_aggregate_z<<<agg_blocks, 256>>>(bufA, off, deg, csr, eps, 2, bufB, n);
    k_gemm_bias_lrelu<<<gemm_blocks, 256, smem_gemm>>>(bufB, W1 + 2 * D * D, b1 + 2 * D, bufA, n);
    k_gemm_bias_lrelu<<<gemm_blocks, 256, smem_gemm>>>(bufA, W2 + 2 * D * D, b2 + 2 * D, emb, n);

    // ---- output projection ----
    k_out_proj<<<agg_blocks, 256>>>(emb, Wout, bout, nout, n);
}

// round 3
// speedup vs baseline: 1.3328x; 1.3328x over previous
#include <cuda_runtime.h>
#include <cuda_bf16.h>
#include <cstdint>

#define N_MAX 100000
#define E_MAX 1600000
#define D 128

// ---------------- scratch (device globals; no allocation allowed) ----------
__device__ float g_bufA[N_MAX * D];
__device__ float g_bufB[N_MAX * D];
__device__ int   g_deg[N_MAX];
__device__ int   g_off[N_MAX];
__device__ int   g_cursor[N_MAX];
__device__ int   g_csr[E_MAX];
__device__ int   g_bsums[128];
// pre-split, pre-swizzled bf16 weight images: [layer][W1/W2][hi/lo][32KB]
__device__ __align__(16) unsigned char g_wimg[3][2][2][32768];

// ---------------- helpers ----------------------------------------------------
__device__ __forceinline__ uint32_t smem_u32(const void* p) {
    uint32_t a;
    asm("{ .reg .u64 t; cvta.to.shared.u64 t, %1; cvt.u32.u64 %0, t; }" : "=r"(a) : "l"(p));
    return a;
}

// split fp32 pair -> packed bf16x2 hi + bf16x2 lo
__device__ __forceinline__ void split2(float a, float b, uint32_t& h, uint32_t& l) {
    __nv_bfloat16 ha = __float2bfloat16(a), hb = __float2bfloat16(b);
    float ra = a - __bfloat162float(ha), rb = b - __bfloat162float(hb);
    __nv_bfloat16 la = __float2bfloat16(ra), lb = __float2bfloat16(rb);
    h = (uint32_t)(*(uint16_t*)&ha) | ((uint32_t)(*(uint16_t*)&hb) << 16);
    l = (uint32_t)(*(uint16_t*)&la) | ((uint32_t)(*(uint16_t*)&lb) << 16);
}

__device__ __forceinline__ void mma16816(float* d, uint32_t a0, uint32_t a1,
                                         uint32_t a2, uint32_t a3,
                                         uint32_t b0, uint32_t b1) {
    asm volatile(
        "mma.sync.aligned.m16n8k16.row.col.f32.bf16.bf16.f32 "
        "{%0,%1,%2,%3}, {%4,%5,%6,%7}, {%8,%9}, {%0,%1,%2,%3};"
        : "+f"(d[0]), "+f"(d[1]), "+f"(d[2]), "+f"(d[3])
        : "r"(a0), "r"(a1), "r"(a2), "r"(a3), "r"(b0), "r"(b1));
}

// ---------------- CSR build -------------------------------------------------
__global__ void k_count_deg(const int* __restrict__ dst, int* __restrict__ deg, int e) {
    int i = blockIdx.x * blockDim.x + threadIdx.x;
    if (i < e) atomicAdd(&deg[dst[i]], 1);
}

__global__ void k_scan_block(const int* __restrict__ deg, int* __restrict__ off,
                             int* __restrict__ bsums, int n) {
    __shared__ int warp_sums[32];
    int tid = threadIdx.x;
    int gid = blockIdx.x * 1024 + tid;
    int v = (gid < n) ? deg[gid] : 0;
    int x = v;
#pragma unroll
    for (int s = 1; s < 32; s <<= 1) {
        int y = __shfl_up_sync(0xffffffffu, x, s);
        if ((tid & 31) >= s) x += y;
    }
    if ((tid & 31) == 31) warp_sums[tid >> 5] = x;
    __syncthreads();
    if (tid < 32) {
        int w = warp_sums[tid];
        int xw = w;
#pragma unroll
        for (int s = 1; s < 32; s <<= 1) {
            int y = __shfl_up_sync(0xffffffffu, xw, s);
            if (tid >= s) xw += y;
        }
        warp_sums[tid] = xw - w;
        if (tid == 31) bsums[blockIdx.x] = xw;
    }
    __syncthreads();
    int excl = x - v + warp_sums[tid >> 5];
    if (gid < n) off[gid] = excl;
}

__global__ void k_add_offsets(int* __restrict__ off, int* __restrict__ cursor,
                              const int* __restrict__ bsums, int n) {
    __shared__ int sbase;
    int g = blockIdx.x >> 2;  // which 1024-group this 256-block belongs to
    if (threadIdx.x < 32) {
        int s = 0;
        for (int j = threadIdx.x; j < g; j += 32) s += bsums[j];
#pragma unroll
        for (int sh = 16; sh > 0; sh >>= 1) s += __shfl_xor_sync(0xffffffffu, s, sh);
        if (threadIdx.x == 0) sbase = s;
    }
    __syncthreads();
    int i = blockIdx.x * blockDim.x + threadIdx.x;
    if (i < n) {
        int o = off[i] + sbase;
        off[i] = o;
        cursor[i] = o;
    }
}

__global__ void k_csr_fill(const int* __restrict__ src, const int* __restrict__ dst,
                           int* __restrict__ cursor, int* __restrict__ csr, int e) {
    int i = blockIdx.x * blockDim.x + threadIdx.x;
    if (i < e) {
        int pos = atomicAdd(&cursor[dst[i]], 1);
        csr[pos] = src[i];
    }
}

// ---------------- weight conversion -----------------------------------------
// fp32 W[k][n] -> bf16 hi/lo stored row-major [k][n] with 16B-chunk XOR swizzle:
// byte(k,n) = k*256 + (((n>>3) ^ (k&7)) << 4) + ((n&7)<<1)
__global__ void k_wconv(const float* __restrict__ W1, const float* __restrict__ W2) {
    int b = blockIdx.x;  // 0..5 : layer = b>>1, which = b&1
    const float* W = ((b & 1) ? W2 : W1) + (b >> 1) * D * D;
    unsigned char* hi = g_wimg[b >> 1][b & 1][0];
    unsigned char* lo = g_wimg[b >> 1][b & 1][1];
    for (int i = threadIdx.x; i < D * D; i += blockDim.x) {
        int k = i >> 7, nn = i & 127;
        float x = W[k * 128 + nn];
        __nv_bfloat16 h = __float2bfloat16(x);
        float r = x - __bfloat162float(h);
        __nv_bfloat16 l = __float2bfloat16(r);
        uint32_t off = (uint32_t)k * 256 + ((((nn >> 3) ^ (k & 7)) & 15) << 4)
                     + ((nn & 7) << 1);
        *(__nv_bfloat16*)(hi + off) = h;
        *(__nv_bfloat16*)(lo + off) = l;
    }
}

// ---------------- aggregation: z = (1+eps)*h + mean_{nbr} h[nbr] ------------
__global__ void k_aggregate_z(const float* __restrict__ h,
                              const int* __restrict__ off,
                              const int* __restrict__ deg,
                              const int* __restrict__ csr,
                              const float* __restrict__ eps, int l,
                              float* __restrict__ z, int n) {
    int warp = (blockIdx.x * blockDim.x + threadIdx.x) >> 5;
    int lane = threadIdx.x & 31;
    if (warp >= n) return;
    int start = off[warp];
    int d = deg[warp];
    float inv = 1.0f / (float)((d > 0) ? d : 1);
    const float4* h4 = (const float4*)h;

    float4 acc = make_float4(0.f, 0.f, 0.f, 0.f);
    int j = 0;
    for (; j + 4 <= d; j += 4) {
        int nb0 = csr[start + j + 0];
        int nb1 = csr[start + j + 1];
        int nb2 = csr[start + j + 2];
        int nb3 = csr[start + j + 3];
        float4 v0 = __ldg(&h4[nb0 * 32 + lane]);
        float4 v1 = __ldg(&h4[nb1 * 32 + lane]);
        float4 v2 = __ldg(&h4[nb2 * 32 + lane]);
        float4 v3 = __ldg(&h4[nb3 * 32 + lane]);
        acc.x += v0.x + v1.x + v2.x + v3.x;
        acc.y += v0.y + v1.y + v2.y + v3.y;
        acc.z += v0.z + v1.z + v2.z + v3.z;
        acc.w += v0.w + v1.w + v2.w + v3.w;
    }
    for (; j < d; ++j) {
        int nb = csr[start + j];
        float4 v = __ldg(&h4[nb * 32 + lane]);
        acc.x += v.x; acc.y += v.y; acc.z += v.z; acc.w += v.w;
    }
    float e1 = 1.0f + eps[l];
    float4 hv = h4[warp * 32 + lane];
    float4 zz;
    zz.x = e1 * hv.x + inv * acc.x;
    zz.y = e1 * hv.y + inv * acc.y;
    zz.z = e1 * hv.z + inv * acc.z;
    zz.w = e1 * hv.w + inv * acc.w;
    ((float4*)z)[warp * 32 + lane] = zz;
}

// ---------------- fused MLP: Out = lrelu(lrelu(A@W1+b1)@W2+b2) --------------
// mma.sync m16n8k16 bf16, hi/lo split (3 passes), 256 threads, 128x128 tile.
// A smem: row-major, 272B row stride (conflict-free for ldmatrix + STS).
// W smem: row-major [k][n], 256B rows, 16B-chunk XOR swizzle by (k&7).
#define OFF_BIAS1 0
#define OFF_BIAS2 512
#define OFF_AHI   1024
#define A_STRIDE  272
#define OFF_ALO   (OFF_AHI + 128 * A_STRIDE)             // 35840
#define OFF_W1HI  (OFF_ALO + 128 * A_STRIDE)             // 70656
#define OFF_W1LO  (OFF_W1HI + 32768)
#define OFF_W2HI  (OFF_W1LO + 32768)
#define OFF_W2LO  (OFF_W2HI + 32768)
#define SMEM_FUSED (OFF_W2LO + 32768)                    // 201728

struct MmaCtx {
    uint32_t smem_base;
    uint32_t aRowByte;   // per-thread A ldmatrix offset within A image
    uint32_t bRowByte;   // per-thread B row byte (k*256)
    uint32_t bChunkXor;  // (k&7)
    uint32_t bnHalf;     // 0/1 : n +8 half selector
};

__device__ __forceinline__ void mma_stage(float acc[16][4], const MmaCtx& cx,
                                          uint32_t aHi, uint32_t aLo,
                                          uint32_t wHi, uint32_t wLo) {
#pragma unroll
    for (int pass = 0; pass < 3; ++pass) {
        uint32_t aBase = cx.smem_base + ((pass == 2) ? aLo : aHi) + cx.aRowByte;
        uint32_t wBase = cx.smem_base + ((pass == 1) ? wLo : wHi) + cx.bRowByte;
#pragma unroll
        for (int ks = 0; ks < 8; ++ks) {
            uint32_t a0, a1, a2, a3;
            asm volatile(
                "ldmatrix.sync.aligned.m8n8.x4.shared.b16 {%0,%1,%2,%3}, [%4];"
                : "=r"(a0), "=r"(a1), "=r"(a2), "=r"(a3)
                : "r"(aBase + ks * 32));
#pragma unroll
            for (int j = 0; j < 8; ++j) {
                uint32_t chunk = ((uint32_t)(j * 2) + cx.bnHalf) ^ cx.bChunkXor;
                uint32_t b0, b1, b2, b3;
                asm volatile(
                    "ldmatrix.sync.aligned.m8n8.x4.trans.shared.b16 {%0,%1,%2,%3}, [%4];"
                    : "=r"(b0), "=r"(b1), "=r"(b2), "=r"(b3)
                    : "r"(wBase + ks * 4096 + chunk * 16));
                mma16816(acc[2 * j], a0, a1, a2, a3, b0, b1);
                mma16816(acc[2 * j + 1], a0, a1, a2, a3, b2, b3);
            }
        }
    }
}

__global__ void __launch_bounds__(256, 1)
k_fused_mlp(const float* __restrict__ Ain,
            const unsigned char* __restrict__ w1hi, const unsigned char* __restrict__ w1lo,
            const unsigned char* __restrict__ w2hi, const unsigned char* __restrict__ w2lo,
            const float* __restrict__ b1, const float* __restrict__ b2,
            float* __restrict__ Out, int n) {
    extern __shared__ unsigned char sm[];
    uint32_t smem_base = smem_u32(sm);
    int t = threadIdx.x, w = t >> 5, lane = t & 31;
    int row0 = blockIdx.x * 128;

    // biases
    if (t < 128) {
        ((float*)(sm + OFF_BIAS1))[t] = b1[t];
        ((float*)(sm + OFF_BIAS2))[t] = b2[t];
    }
    // copy pre-swizzled W images (4 x 32KB = 8192 uint4)
    {
        const uint4* s1 = (const uint4*)w1hi;
        const uint4* s2 = (const uint4*)w1lo;
        const uint4* s3 = (const uint4*)w2hi;
        const uint4* s4 = (const uint4*)w2lo;
        uint4* d1 = (uint4*)(sm + OFF_W1HI);
        uint4* d2 = (uint4*)(sm + OFF_W1LO);
        uint4* d3 = (uint4*)(sm + OFF_W2HI);
        uint4* d4 = (uint4*)(sm + OFF_W2LO);
#pragma unroll
        for (int i = 0; i < 8; ++i) {
            int j = t + i * 256;
            d1[j] = __ldg(&s1[j]);
            d2[j] = __ldg(&s2[j]);
            d3[j] = __ldg(&s3[j]);
            d4[j] = __ldg(&s4[j]);
        }
    }
    // load A tile fp32, split hi/lo bf16, store to padded row-major smem
    {
        const float4* A4 = (const float4*)Ain;
#pragma unroll
        for (int i = 0; i < 16; ++i) {
            int j = t + i * 256;          // 0..4095
            int row = j >> 5, ch = j & 31;
            int gr = row0 + row;
            float4 v = make_float4(0.f, 0.f, 0.f, 0.f);
            if (gr < n) v = __ldg(&A4[(size_t)gr * 32 + ch]);
            uint32_t h01, h23, l01, l23;
            split2(v.x, v.y, h01, l01);
            split2(v.z, v.w, h23, l23);
            *(uint2*)(sm + OFF_AHI + row * A_STRIDE + ch * 8) = make_uint2(h01, h23);
            *(uint2*)(sm + OFF_ALO + row * A_STRIDE + ch * 8) = make_uint2(l01, l23);
        }
    }
    __syncthreads();

    // per-thread ldmatrix address components
    MmaCtx cx;
    cx.smem_base = smem_base;
    {
        uint32_t mOff = ((lane >> 3) & 1) * 8;   // +8 rows for groups 1,3
        uint32_t kHalf = (lane >> 4) & 1;        // +8 k for groups 2,3
        cx.aRowByte = (w * 16 + (lane & 7) + mOff) * A_STRIDE + kHalf * 16;
        uint32_t bk = (lane & 7) + ((lane >> 3) & 1) * 8;
        cx.bRowByte = bk * 256;
        cx.bChunkXor = bk & 7;
        cx.bnHalf = (lane >> 4) & 1;
    }

    float acc[16][4];
#pragma unroll
    for (int j = 0; j < 16; ++j)
#pragma unroll
        for (int q = 0; q < 4; ++q) acc[j][q] = 0.f;

    // ---- stage 1: z = lrelu(A @ W1 + b1) ----
    mma_stage(acc, cx, OFF_AHI, OFF_ALO, OFF_W1HI, OFF_W1LO);

    // epilogue 1: bias + lrelu, split to bf16 hi/lo back into A smem
    // (each warp owns its 16 A rows -> warp-local sync only)
    const float* bias1 = (const float*)(sm + OFF_BIAS1);
    int rowInWarp = lane >> 2;          // 0..7
    int colBase = (lane & 3) * 2;
    int myRow0 = w * 16 + rowInWarp;
    int myRow1 = myRow0 + 8;
#pragma unroll
    for (int j = 0; j < 16; ++j) {
        int c = j * 8 + colBase;
        float x0 = acc[j][0] + bias1[c];
        float x1 = acc[j][1] + bias1[c + 1];
        float y0 = acc[j][2] + bias1[c];
        float y1 = acc[j][3] + bias1[c + 1];
        x0 = (x0 > 0.f) ? x0 : 0.01f * x0;
        x1 = (x1 > 0.f) ? x1 : 0.01f * x1;
        y0 = (y0 > 0.f) ? y0 : 0.01f * y0;
        y1 = (y1 > 0.f) ? y1 : 0.01f * y1;
        uint32_t h, l;
        split2(x0, x1, h, l);
        *(uint32_t*)(sm + OFF_AHI + myRow0 * A_STRIDE + c * 2) = h;
        *(uint32_t*)(sm + OFF_ALO + myRow0 * A_STRIDE + c * 2) = l;
        split2(y0, y1, h, l);
        *(uint32_t*)(sm + OFF_AHI + myRow1 * A_STRIDE + c * 2) = h;
        *(uint32_t*)(sm + OFF_ALO + myRow1 * A_STRIDE + c * 2) = l;
        acc[j][0] = acc[j][1] = acc[j][2] = acc[j][3] = 0.f;
    }
    __syncwarp();

    // ---- stage 2: out = lrelu(z @ W2 + b2) ----
    mma_stage(acc, cx, OFF_AHI, OFF_ALO, OFF_W2HI, OFF_W2LO);

    // epilogue 2: bias + lrelu, fp32 store to gmem
    const float* bias2 = (const float*)(sm + OFF_BIAS2);
    int gr0 = row0 + myRow0;
    int gr1 = row0 + myRow1;
#pragma unroll
    for (int j = 0; j < 16; ++j) {
        int c = j * 8 + colBase;
        float x0 = acc[j][0] + bias2[c];
        float x1 = acc[j][1] + bias2[c + 1];
        float y0 = acc[j][2] + bias2[c];
        float y1 = acc[j][3] + bias2[c + 1];
        x0 = (x0 > 0.f) ? x0 : 0.01f * x0;
        x1 = (x1 > 0.f) ? x1 : 0.01f * x1;
        y0 = (y0 > 0.f) ? y0 : 0.01f * y0;
        y1 = (y1 > 0.f) ? y1 : 0.01f * y1;
        if (gr0 < n) *(float2*)(Out + (size_t)gr0 * 128 + c) = make_float2(x0, x1);
        if (gr1 < n) *(float2*)(Out + (size_t)gr1 * 128 + c) = make_float2(y0, y1);
    }
}

// ---------------- output projection ------------------------------------------
__global__ void k_out_proj(const float* __restrict__ emb,
                           const float* __restrict__ Wout,
                           const float* __restrict__ bout,
                           float* __restrict__ nout, int n) {
    int warp = (blockIdx.x * blockDim.x + threadIdx.x) >> 5;
    int lane = threadIdx.x & 31;
    if (warp >= n) return;
    float4 h = ((const float4*)emb)[warp * 32 + lane];
    int d0 = lane * 4;
    float s0 = h.x * Wout[(d0 + 0) * 2 + 0] + h.y * Wout[(d0 + 1) * 2 + 0]
             + h.z * Wout[(d0 + 2) * 2 + 0] + h.w * Wout[(d0 + 3) * 2 + 0];
    float s1 = h.x * Wout[(d0 + 0) * 2 + 1] + h.y * Wout[(d0 + 1) * 2 + 1]
             + h.z * Wout[(d0 + 2) * 2 + 1] + h.w * Wout[(d0 + 3) * 2 + 1];
#pragma unroll
    for (int s = 16; s > 0; s >>= 1) {
        s0 += __shfl_xor_sync(0xffffffffu, s0, s);
        s1 += __shfl_xor_sync(0xffffffffu, s1, s);
    }
    if (lane == 0) {
        nout[warp * 2 + 0] = s0 + bout[0];
        nout[warp * 2 + 1] = s1 + bout[1];
    }
}

// ---------------- launch ------------------------------------------------------
extern "C" void kernel_launch(void* const* d_in, const int* in_sizes, int n_in,
                              void* d_out, int out_size) {
    const float* x    = (const float*)d_in[0];
    const int*   src  = (const int*)d_in[1];
    const int*   dst  = (const int*)d_in[2];
    const float* W1   = (const float*)d_in[3];
    const float* b1   = (const float*)d_in[4];
    const float* W2   = (const float*)d_in[5];
    const float* b2   = (const float*)d_in[6];
    const float* eps  = (const float*)d_in[7];
    const float* Wout = (const float*)d_in[8];
    const float* bout = (const float*)d_in[9];

    const int n = in_sizes[0] / D;
    const int e = in_sizes[1];

    float* nout = (float*)d_out;                 // [n, 2]
    float* emb  = (float*)d_out + (size_t)n * 2; // [n, 128]

    float *bufA, *bufB;
    int *deg, *off, *cursor, *csr, *bsums;
    unsigned char* wimg;
    cudaGetSymbolAddress((void**)&bufA,   g_bufA);
    cudaGetSymbolAddress((void**)&bufB,   g_bufB);
    cudaGetSymbolAddress((void**)&deg,    g_deg);
    cudaGetSymbolAddress((void**)&off,    g_off);
    cudaGetSymbolAddress((void**)&cursor, g_cursor);
    cudaGetSymbolAddress((void**)&csr,    g_csr);
    cudaGetSymbolAddress((void**)&bsums,  g_bsums);
    cudaGetSymbolAddress((void**)&wimg,   g_wimg);

    cudaFuncSetAttribute(k_fused_mlp,
                         cudaFuncAttributeMaxDynamicSharedMemorySize, SMEM_FUSED);

    // ---- CSR build ----
    cudaMemsetAsync(deg, 0, n * sizeof(int));
    k_count_deg<<<(e + 255) / 256, 256>>>(dst, deg, e);
    int nb = (n + 1023) / 1024;
    k_scan_block<<<nb, 1024>>>(deg, off, bsums, n);
    k_add_offsets<<<(n + 255) / 256, 256>>>(off, cursor, bsums, n);
    k_csr_fill<<<(e + 255) / 256, 256>>>(src, dst, cursor, csr, e);

    // ---- weight conversion (once per launch) ----
    k_wconv<<<6, 256>>>(W1, W2);

    const int agg_blocks = (n * 32 + 255) / 256;
    const int mlp_blocks = (n + 127) / 128;

    auto wp = [&](int l, int which, int part) -> unsigned char* {
        return wimg + (((size_t)l * 2 + which) * 2 + part) * 32768;
    };

    // layer 0
    k_aggregate_z<<<agg_blocks, 256>>>(x, off, deg, csr, eps, 0, bufA, n);
    k_fused_mlp<<<mlp_blocks, 256, SMEM_FUSED>>>(bufA,
        wp(0, 0, 0), wp(0, 0, 1), wp(0, 1, 0), wp(0, 1, 1),
        b1 + 0 * D, b2 + 0 * D, bufB, n);

    // layer 1
    k_aggregate_z<<<agg_blocks, 256>>>(bufB, off, deg, csr, eps, 1, bufA, n);
    k_fused_mlp<<<mlp_blocks, 256, SMEM_FUSED>>>(bufA,
        wp(1, 0, 0), wp(1, 0, 1), wp(1, 1, 0), wp(1, 1, 1),
        b1 + 1 * D, b2 + 1 * D, bufB, n);

    // layer 2 -> emb (output buffer)
    k_aggregate_z<<<agg_blocks, 256>>>(bufB, off, deg, csr, eps, 2, bufA, n);
    k_fused_mlp<<<mlp_blocks, 256, SMEM_FUSED>>>(bufA,
        wp(2, 0, 0), wp(2, 0, 1), wp(2, 1, 0), wp(2, 1, 1),
        b1 + 2 * D, b2 + 2 * D, emb, n);

    // ---- output projection ----
    k_out_proj<<<agg_blocks, 256>>>(emb, Wout, bout, nout, n);
}